// round 7
// baseline (speedup 1.0000x reference)
#include <cuda_runtime.h>
#include <cuda_bf16.h>
#include <cstdint>

// Problem constants
#define BATCH_  4096
#define IDIM_   256
#define ODIM_   512
#define KDIM_   512          // concat(silu, spline) contraction dim
#define NKNOTS_ 64
#define NBASIS_ 60           // NUM_KNOTS - DEGREE - 1
#define KT_     (KDIM_ / 8)  // 64 k-tiles of 8
#define MT_     (BATCH_ / 16)
#define NT_     (ODIM_ / 8)

// Scratch (allocation-free rule: __device__ globals).
// actP: A matrix in m16n8k8 A-fragment order: [mtile][ktile][lane*4 + e]
// WP:   W matrix in m16n8k8 B-fragment order: [ntile][ktile][lane*2 + e]
__device__ float g_actP[MT_ * KT_ * 128];   // 8 MB
__device__ float g_WP[NT_ * KT_ * 64];      // 1 MB

__device__ __forceinline__ float f2tf32(float v) {
    uint32_t r;
    asm("cvt.rna.tf32.f32 %0, %1;" : "=r"(r) : "f"(v));
    return __uint_as_float(r);
}

// m16n8k8 A fragment: a0=(g,t) a1=(g+8,t) a2=(g,t+4) a3=(g+8,t+4); g=lane/4, t=lane%4
__device__ __forceinline__ int actp_idx(int row, int col) {
    int mt = row >> 4, r = row & 15;
    int kt = col >> 3, c = col & 7;
    int l = ((r & 7) << 2) | (c & 3);
    int e = (r >> 3) | ((c >> 2) << 1);
    return ((mt * KT_ + kt) << 7) | (l << 2) | e;
}

// m16n8k8 B fragment: b0=(k=t, n=g) b1=(k=t+4, n=g)
__device__ __forceinline__ int wp_idx(int k, int n) {
    int nt = n >> 3, g = n & 7;
    int kt = k >> 3, c = k & 7;
    int l = (g << 2) | (c & 3);
    int e = c >> 2;
    return ((nt * KT_ + kt) << 6) | (l << 1) | e;
}

__global__ void prep_kernel(const float* __restrict__ x,
                            const float* __restrict__ wb,
                            const float* __restrict__ ws,
                            const float* __restrict__ cps,
                            const float* __restrict__ knots) {
    int gid = blockIdx.x * blockDim.x + threadIdx.x;
    const int total_act = BATCH_ * IDIM_;  // 1048576
    if (gid < total_act) {
        int b = gid >> 8;       // IDIM_ = 256
        int i = gid & 255;
        float xv = x[gid];

        // silu
        float sil = xv / (1.f + __expf(-xv));

        // cubic B-spline on uniform knots: closed-form 4-tap evaluation
        float k0v = __ldg(knots);
        float k63 = __ldg(knots + NKNOTS_ - 1);
        float sp = 0.f;
        if (xv >= k0v && xv < k63) {
            float inv_h = (float)(NKNOTS_ - 1) / (k63 - k0v);
            int j = (int)floorf((xv - k0v) * inv_h);
            j = min(NKNOTS_ - 2, max(0, j));
            float kj  = __ldg(knots + j);
            float kj1 = __ldg(knots + j + 1);
            if (xv < kj)        { j--; kj1 = kj;  kj  = __ldg(knots + j); }
            else if (xv >= kj1) { j++; kj  = kj1; kj1 = __ldg(knots + j + 1); }
            j = min(NKNOTS_ - 2, max(3, j));
            float u  = (xv - kj) / (kj1 - kj);
            float um = 1.f - u;
            float u2 = u * u, u3 = u2 * u;
            float w0 = um * um * um * (1.f / 6.f);                       // k = j-3
            float w1 = (3.f * u3 - 6.f * u2 + 4.f) * (1.f / 6.f);        // k = j-2
            float w2 = (-3.f * u3 + 3.f * u2 + 3.f * u + 1.f) * (1.f / 6.f); // k = j-1
            float w3 = u3 * (1.f / 6.f);                                 // k = j
            const float* cr = cps + i * NKNOTS_;
            sp = w0 * __ldg(cr + j - 3);
            if (j - 2 < NBASIS_) sp += w1 * __ldg(cr + j - 2);
            if (j - 1 < NBASIS_) sp += w2 * __ldg(cr + j - 1);
            if (j     < NBASIS_) sp += w3 * __ldg(cr + j);
        }

        g_actP[actp_idx(b, i)]          = f2tf32(sil);
        g_actP[actp_idx(b, IDIM_ + i)]  = f2tf32(sp);
    } else {
        int gid2 = gid - total_act;      // 0 .. 512*512-1
        int k = gid2 >> 9;               // ODIM_ = 512
        int n = gid2 & 511;
        float v = (k < IDIM_) ? wb[k * ODIM_ + n] : ws[(k - IDIM_) * ODIM_ + n];
        g_WP[wp_idx(k, n)] = f2tf32(v);
    }
}

__device__ __forceinline__ void mma_tf32(float* c, const float4& a, const float2& b) {
    asm volatile(
        "mma.sync.aligned.m16n8k8.row.col.f32.tf32.tf32.f32 "
        "{%0,%1,%2,%3}, {%4,%5,%6,%7}, {%8,%9}, {%0,%1,%2,%3};"
        : "+f"(c[0]), "+f"(c[1]), "+f"(c[2]), "+f"(c[3])
        : "r"(__float_as_uint(a.x)), "r"(__float_as_uint(a.y)),
          "r"(__float_as_uint(a.z)), "r"(__float_as_uint(a.w)),
          "r"(__float_as_uint(b.x)), "r"(__float_as_uint(b.y)));
}

// Block tile 128(M) x 128(N); 8 warps as 4(M) x 2(N); warp tile 32x64.
// Fragments loaded directly from pre-permuted global (L2-resident), no smem.
__global__ void __launch_bounds__(256) gemm_kernel(float* __restrict__ out) {
    const int lane = threadIdx.x & 31;
    const int warp = threadIdx.x >> 5;
    const int wm = warp >> 1;              // 0..3
    const int wn = warp & 1;               // 0..1
    const int mt0 = blockIdx.y * 8 + wm * 2;    // 2 m-tiles / warp
    const int nt0 = blockIdx.x * 16 + wn * 8;   // 8 n-tiles / warp

    float acc[2][8][4] = {};

    const float4* A4 = reinterpret_cast<const float4*>(g_actP);
    const float2* B2 = reinterpret_cast<const float2*>(g_WP);

    int aIdx[2], bIdx[8];
#pragma unroll
    for (int im = 0; im < 2; im++) aIdx[im] = (mt0 + im) * KT_ * 32 + lane;
#pragma unroll
    for (int in = 0; in < 8; in++) bIdx[in] = (nt0 + in) * KT_ * 32 + lane;

    float4 a_c[2];
    float2 b_c[8];
#pragma unroll
    for (int im = 0; im < 2; im++) a_c[im] = __ldg(A4 + aIdx[im]);
#pragma unroll
    for (int in = 0; in < 8; in++) b_c[in] = __ldg(B2 + bIdx[in]);

#pragma unroll 4
    for (int kt = 0; kt < KT_; kt++) {
        float4 a_n[2];
        float2 b_n[8];
        int nk = (kt + 1 < KT_) ? (kt + 1) : kt;
#pragma unroll
        for (int im = 0; im < 2; im++) a_n[im] = __ldg(A4 + aIdx[im] + nk * 32);
#pragma unroll
        for (int in = 0; in < 8; in++) b_n[in] = __ldg(B2 + bIdx[in] + nk * 32);

#pragma unroll
        for (int im = 0; im < 2; im++)
#pragma unroll
            for (int in = 0; in < 8; in++)
                mma_tf32(acc[im][in], a_c[im], b_c[in]);

#pragma unroll
        for (int im = 0; im < 2; im++) a_c[im] = a_n[im];
#pragma unroll
        for (int in = 0; in < 8; in++) b_c[in] = b_n[in];
    }

    // Epilogue: c0=(g,2t) c1=(g,2t+1) c2=(g+8,2t) c3=(g+8,2t+1)
    const int g = lane >> 2, t = lane & 3;
#pragma unroll
    for (int im = 0; im < 2; im++) {
        int row = (mt0 + im) * 16 + g;
#pragma unroll
        for (int in = 0; in < 8; in++) {
            int col = (nt0 + in) * 8 + t * 2;
            float2 v0 = make_float2(acc[im][in][0], acc[im][in][1]);
            float2 v1 = make_float2(acc[im][in][2], acc[im][in][3]);
            *reinterpret_cast<float2*>(out + (size_t)row * ODIM_ + col) = v0;
            *reinterpret_cast<float2*>(out + (size_t)(row + 8) * ODIM_ + col) = v1;
        }
    }
}

extern "C" void kernel_launch(void* const* d_in, const int* in_sizes, int n_in,
                              void* d_out, int out_size) {
    const float* x     = (const float*)d_in[0];
    const float* wb    = (const float*)d_in[1];
    const float* ws    = (const float*)d_in[2];
    const float* cps   = (const float*)d_in[3];
    const float* knots = (const float*)d_in[4];
    float* out = (float*)d_out;

    // 4096*256 act elements + 512*512 W elements = 1310720 = 5120 * 256
    prep_kernel<<<5120, 256>>>(x, wb, ws, cps, knots);
    gemm_kernel<<<dim3(ODIM_ / 128, BATCH_ / 128), 256>>>(out);
}

// round 8
// speedup vs baseline: 1.0580x; 1.0580x over previous
#include <cuda_runtime.h>
#include <cuda_bf16.h>
#include <cstdint>

// Problem constants
#define BATCH_  4096
#define IDIM_   256
#define ODIM_   512
#define KDIM_   512          // concat(silu, spline) contraction dim
#define NKNOTS_ 64
#define NBASIS_ 60           // NUM_KNOTS - DEGREE - 1
#define KT_     (KDIM_ / 8)  // 64 k-tiles of 8
#define MT_     (BATCH_ / 16)
#define NT_     (ODIM_ / 8)

// Scratch (allocation-free rule: __device__ globals).
// actP: A matrix in m16n8k8 A-fragment order: [mtile][ktile][lane*4 + e]
// WP:   W matrix in m16n8k8 B-fragment order: [ntile][ktile][lane*2 + e]
__device__ float g_actP[MT_ * KT_ * 128];   // 8 MB
__device__ float g_WP[NT_ * KT_ * 64];      // 1 MB

__device__ __forceinline__ float f2tf32(float v) {
    uint32_t r;
    asm("cvt.rna.tf32.f32 %0, %1;" : "=r"(r) : "f"(v));
    return __uint_as_float(r);
}

// m16n8k8 A fragment: a0=(g,t) a1=(g+8,t) a2=(g,t+4) a3=(g+8,t+4); g=lane/4, t=lane%4
__device__ __forceinline__ int actp_idx(int row, int col) {
    int mt = row >> 4, r = row & 15;
    int kt = col >> 3, c = col & 7;
    int l = ((r & 7) << 2) | (c & 3);
    int e = (r >> 3) | ((c >> 2) << 1);
    return ((mt * KT_ + kt) << 7) | (l << 2) | e;
}

// m16n8k8 B fragment: b0=(k=t, n=g) b1=(k=t+4, n=g)
__device__ __forceinline__ int wp_idx(int k, int n) {
    int nt = n >> 3, g = n & 7;
    int kt = k >> 3, c = k & 7;
    int l = (g << 2) | (c & 3);
    int e = c >> 2;
    return ((nt * KT_ + kt) << 6) | (l << 1) | e;
}

__global__ void prep_kernel(const float* __restrict__ x,
                            const float* __restrict__ wb,
                            const float* __restrict__ ws,
                            const float* __restrict__ cps,
                            const float* __restrict__ knots) {
    int gid = blockIdx.x * blockDim.x + threadIdx.x;
    const int total_act = BATCH_ * IDIM_;  // 1048576
    if (gid < total_act) {
        int b = gid >> 8;       // IDIM_ = 256
        int i = gid & 255;
        float xv = x[gid];

        // silu
        float sil = xv / (1.f + __expf(-xv));

        // cubic B-spline on uniform knots: closed-form 4-tap evaluation
        float k0v = __ldg(knots);
        float k63 = __ldg(knots + NKNOTS_ - 1);
        float sp = 0.f;
        if (xv >= k0v && xv < k63) {
            float inv_h = (float)(NKNOTS_ - 1) / (k63 - k0v);
            int j = (int)floorf((xv - k0v) * inv_h);
            j = min(NKNOTS_ - 2, max(0, j));
            float kj  = __ldg(knots + j);
            float kj1 = __ldg(knots + j + 1);
            if (xv < kj)        { j--; kj1 = kj;  kj  = __ldg(knots + j); }
            else if (xv >= kj1) { j++; kj  = kj1; kj1 = __ldg(knots + j + 1); }
            j = min(NKNOTS_ - 2, max(3, j));
            float u  = (xv - kj) / (kj1 - kj);
            float um = 1.f - u;
            float u2 = u * u, u3 = u2 * u;
            float w0 = um * um * um * (1.f / 6.f);                       // k = j-3
            float w1 = (3.f * u3 - 6.f * u2 + 4.f) * (1.f / 6.f);        // k = j-2
            float w2 = (-3.f * u3 + 3.f * u2 + 3.f * u + 1.f) * (1.f / 6.f); // k = j-1
            float w3 = u3 * (1.f / 6.f);                                 // k = j
            const float* cr = cps + i * NKNOTS_;
            sp = w0 * __ldg(cr + j - 3);
            if (j - 2 < NBASIS_) sp += w1 * __ldg(cr + j - 2);
            if (j - 1 < NBASIS_) sp += w2 * __ldg(cr + j - 1);
            if (j     < NBASIS_) sp += w3 * __ldg(cr + j);
        }

        g_actP[actp_idx(b, i)]          = f2tf32(sil);
        g_actP[actp_idx(b, IDIM_ + i)]  = f2tf32(sp);
    } else {
        int gid2 = gid - total_act;      // 0 .. 512*512-1
        int k = gid2 >> 9;               // ODIM_ = 512
        int n = gid2 & 511;
        float v = (k < IDIM_) ? wb[k * ODIM_ + n] : ws[(k - IDIM_) * ODIM_ + n];
        g_WP[wp_idx(k, n)] = f2tf32(v);
    }
}

__device__ __forceinline__ void mma_tf32(float* c, const float4& a, const float2& b) {
    asm volatile(
        "mma.sync.aligned.m16n8k8.row.col.f32.tf32.tf32.f32 "
        "{%0,%1,%2,%3}, {%4,%5,%6,%7}, {%8,%9}, {%0,%1,%2,%3};"
        : "+f"(c[0]), "+f"(c[1]), "+f"(c[2]), "+f"(c[3])
        : "r"(__float_as_uint(a.x)), "r"(__float_as_uint(a.y)),
          "r"(__float_as_uint(a.z)), "r"(__float_as_uint(a.w)),
          "r"(__float_as_uint(b.x)), "r"(__float_as_uint(b.y)));
}

// Block tile 128(M) x 128(N); 8 warps as 4(M) x 2(N); warp tile 32x64.
// Fragments loaded directly from pre-permuted global (L2-resident), no smem.
__global__ void __launch_bounds__(256) gemm_kernel(float* __restrict__ out) {
    const int lane = threadIdx.x & 31;
    const int warp = threadIdx.x >> 5;
    const int wm = warp >> 1;              // 0..3
    const int wn = warp & 1;               // 0..1
    const int mt0 = blockIdx.y * 8 + wm * 2;    // 2 m-tiles / warp
    const int nt0 = blockIdx.x * 16 + wn * 8;   // 8 n-tiles / warp

    float acc[2][8][4] = {};

    const float4* A4 = reinterpret_cast<const float4*>(g_actP);
    const float2* B2 = reinterpret_cast<const float2*>(g_WP);

    int aIdx[2], bIdx[8];
#pragma unroll
    for (int im = 0; im < 2; im++) aIdx[im] = (mt0 + im) * KT_ * 32 + lane;
#pragma unroll
    for (int in = 0; in < 8; in++) bIdx[in] = (nt0 + in) * KT_ * 32 + lane;

    float4 a_c[2];
    float2 b_c[8];
#pragma unroll
    for (int im = 0; im < 2; im++) a_c[im] = __ldg(A4 + aIdx[im]);
#pragma unroll
    for (int in = 0; in < 8; in++) b_c[in] = __ldg(B2 + bIdx[in]);

#pragma unroll 4
    for (int kt = 0; kt < KT_; kt++) {
        float4 a_n[2];
        float2 b_n[8];
        int nk = (kt + 1 < KT_) ? (kt + 1) : kt;
#pragma unroll
        for (int im = 0; im < 2; im++) a_n[im] = __ldg(A4 + aIdx[im] + nk * 32);
#pragma unroll
        for (int in = 0; in < 8; in++) b_n[in] = __ldg(B2 + bIdx[in] + nk * 32);

#pragma unroll
        for (int im = 0; im < 2; im++)
#pragma unroll
            for (int in = 0; in < 8; in++)
                mma_tf32(acc[im][in], a_c[im], b_c[in]);

#pragma unroll
        for (int im = 0; im < 2; im++) a_c[im] = a_n[im];
#pragma unroll
        for (int in = 0; in < 8; in++) b_c[in] = b_n[in];
    }

    // Epilogue: c0=(g,2t) c1=(g,2t+1) c2=(g+8,2t) c3=(g+8,2t+1)
    const int g = lane >> 2, t = lane & 3;
#pragma unroll
    for (int im = 0; im < 2; im++) {
        int row = (mt0 + im) * 16 + g;
#pragma unroll
        for (int in = 0; in < 8; in++) {
            int col = (nt0 + in) * 8 + t * 2;
            float2 v0 = make_float2(acc[im][in][0], acc[im][in][1]);
            float2 v1 = make_float2(acc[im][in][2], acc[im][in][3]);
            *reinterpret_cast<float2*>(out + (size_t)row * ODIM_ + col) = v0;
            *reinterpret_cast<float2*>(out + (size_t)(row + 8) * ODIM_ + col) = v1;
        }
    }
}

extern "C" void kernel_launch(void* const* d_in, const int* in_sizes, int n_in,
                              void* d_out, int out_size) {
    const float* x     = (const float*)d_in[0];
    const float* wb    = (const float*)d_in[1];
    const float* ws    = (const float*)d_in[2];
    const float* cps   = (const float*)d_in[3];
    const float* knots = (const float*)d_in[4];
    float* out = (float*)d_out;

    // 4096*256 act elements + 512*512 W elements = 1310720 = 5120 * 256
    prep_kernel<<<5120, 256>>>(x, wb, ws, cps, knots);
    gemm_kernel<<<dim3(ODIM_ / 128, BATCH_ / 128), 256>>>(out);
}